// round 1
// baseline (speedup 1.0000x reference)
#include <cuda_runtime.h>
#include <cuda_bf16.h>

// GaussianRender: T=64 tiles (8x8) of 64x64 px, K=256 sorted gaussians per tile.
// out[gy][gx][c] = sum_k w_k * col_k, w_k = alpha_k * (1 - sum_{j<k} alpha_j),
// alpha = clip(op * exp(-0.5 * d^T Sigma^{-1} d), 0.01, 0.99)
//
// Strategy: compute-bound (fp32 + MUFU). Per-block: preprocess 256 gaussians
// into smem with folded constants (log2-space opacity, -0.5*log2e * inv-cov).
// Each thread owns 4 pixels in one column (dy stride 4) so the dx-dependent
// terms amortize 4x per gaussian.

#define NTILE  8
#define TS     64
#define KG     256
#define WIMG   512

__device__ __forceinline__ float ex2f(float x) {
    float y; asm("ex2.approx.f32 %0, %1;" : "=f"(y) : "f"(x)); return y;
}
__device__ __forceinline__ float lg2f(float x) {
    float y; asm("lg2.approx.f32 %0, %1;" : "=f"(y) : "f"(x)); return y;
}

__global__ __launch_bounds__(256, 4)
void GaussianRender_kernel(const float* __restrict__ mu,
                           const float* __restrict__ cov,
                           const float* __restrict__ opac,
                           const float* __restrict__ col,
                           const int*   __restrict__ tidx,
                           float*       __restrict__ out)
{
    __shared__ float4 sA[KG];  // mx, my, k1, k2
    __shared__ float4 sB[KG];  // k3, lop, cr, cg
    __shared__ float  sC[KG];  // cb

    const int bid = blockIdx.x;
    const int t   = bid >> 2;        // tile id 0..63
    const int q   = bid & 3;         // quarter of tile (16 rows)
    const int tx  = t & (NTILE - 1);
    const int ty  = t >> 3;
    const int tid = threadIdx.x;

    // ---- preprocess one gaussian per thread into smem ----
    {
        const int g = tidx[t * KG + tid];
        const float a = cov[g * 4 + 0];
        const float b = cov[g * 4 + 1];
        const float c = cov[g * 4 + 2];
        const float d = cov[g * 4 + 3];
        const float det = fmaxf(fmaf(a, d, -b * c), 1e-6f);
        const float inv = 1.0f / det;
        // power(dx,dy) = e * (d*dx^2 - (b+c)*dx*dy + a*dy^2)/det + log2(op)
        const float e  = -0.7213475204444817f;   // -0.5 * log2(e)
        const float k1 = e * d * inv;
        const float k2 = -e * (b + c) * inv;
        const float k3 = e * a * inv;
        const float lop = lg2f(opac[g]);          // op>0; -inf is fine (ex2->0->clamp)
        sA[tid] = make_float4(mu[g * 2 + 0], mu[g * 2 + 1], k1, k2);
        sB[tid] = make_float4(k3, lop, col[g * 3 + 0], col[g * 3 + 1]);
        sC[tid] = col[g * 3 + 2];
    }
    __syncthreads();

    // ---- 4 pixels per thread, same lx, ly stride 4 ----
    const int lx  = tid & 63;
    const int ly0 = q * 16 + (tid >> 6);          // rows ly0, ly0+4, ly0+8, ly0+12
    const float px  = (float)(tx * TS + lx) + 0.5f;
    const float py0 = (float)(ty * TS + ly0) + 0.5f;

    float accR[4] = {0.f, 0.f, 0.f, 0.f};
    float accG[4] = {0.f, 0.f, 0.f, 0.f};
    float accB[4] = {0.f, 0.f, 0.f, 0.f};
    float ssum[4] = {0.f, 0.f, 0.f, 0.f};

    #pragma unroll 4
    for (int k = 0; k < KG; ++k) {
        const float4 A = sA[k];
        const float4 B = sB[k];
        const float  cb = sC[k];

        const float dx  = px - A.x;
        const float u   = fmaf(A.z * dx, dx, B.y);   // k1*dx^2 + lop
        const float k2x = A.w * dx;                  // k2*dx
        float dy = py0 - A.y;

        #pragma unroll
        for (int p = 0; p < 4; ++p) {
            const float tv = fmaf(B.x, dy, k2x);     // k3*dy + k2*dx
            const float pw = fmaf(dy, tv, u);        // full log2-domain exponent
            float al = ex2f(pw);                     // op * exp(-0.5*maha)
            al = fminf(fmaxf(al, 0.01f), 0.99f);
            const float w = fmaf(-al, ssum[p], al);  // alpha * (1 - sum_prev)
            accR[p] = fmaf(w, B.z, accR[p]);
            accG[p] = fmaf(w, B.w, accG[p]);
            accB[p] = fmaf(w, cb,  accB[p]);
            ssum[p] += al;
            dy += 4.0f;
        }
    }

    // ---- write 4 pixels ----
    const int gx  = tx * TS + lx;
    const int gy0 = ty * TS + ly0;
    #pragma unroll
    for (int p = 0; p < 4; ++p) {
        const int o = ((gy0 + 4 * p) * WIMG + gx) * 3;
        out[o + 0] = accR[p];
        out[o + 1] = accG[p];
        out[o + 2] = accB[p];
    }
}

extern "C" void kernel_launch(void* const* d_in, const int* in_sizes, int n_in,
                              void* d_out, int out_size)
{
    const float* mu   = (const float*)d_in[0];
    const float* cov  = (const float*)d_in[1];
    const float* opac = (const float*)d_in[2];
    const float* col  = (const float*)d_in[3];
    const int*   tidx = (const int*)  d_in[4];
    float* out = (float*)d_out;

    // 64 tiles * 4 quarter-tiles = 256 blocks, 256 threads, 4 px/thread
    GaussianRender_kernel<<<256, 256>>>(mu, cov, opac, col, tidx, out);
}